// round 11
// baseline (speedup 1.0000x reference)
#include <cuda_runtime.h>
#include <cuda_bf16.h>
#include <cuda_fp16.h>
#include <stdint.h>
#include <math.h>

#define B_ 8
#define N_ 128
#define M_ 128
#define E_ 256
#define H_ 512

// ---------------- scratch (no allocations allowed) ----------------
__device__ float g_tn[B_ * N_ * E_];   // l2-normalized track features
__device__ float g_dn[B_ * M_ * E_];   // l2-normalized det features
__device__ float g_A [B_ * N_ * H_];   // t_n @ W1[0:E]   + b1
__device__ float g_Bv[B_ * M_ * H_];   // d_m @ W1[E:2E]
// W1c^T single fp16: per 64-k chunk, 512 rows (h) x 128B (64 fp16 k), swizzled
__device__ __align__(16) unsigned char g_W[4 * 65536];

// XOR bits[4:6] of the 128B row offset with (row & 7)
#define SWZ(o) ((o) ^ (((o) >> 3) & 0x70))

__device__ __forceinline__ uint32_t smem_u32(const void* p) {
    uint32_t a;
    asm("{ .reg .u64 t; cvta.to.shared.u64 t, %1; cvt.u32.u64 %0, t; }" : "=r"(a) : "l"(p));
    return a;
}
__device__ __forceinline__ uint32_t pk2h(__half a, __half b) {
    return (uint32_t)__half_as_ushort(a) | ((uint32_t)__half_as_ushort(b) << 16);
}
#define CP_ASYNC16(dst, src) \
    asm volatile("cp.async.cg.shared.global [%0], [%1], 16;" :: "r"(dst), "l"(src) : "memory")
#define CP_COMMIT() asm volatile("cp.async.commit_group;" ::: "memory")
#define CP_WAIT0()  asm volatile("cp.async.wait_group 0;" ::: "memory")

#define LDMX4(r0, r1, r2, r3, addr) \
    asm volatile("ldmatrix.sync.aligned.m8n8.x4.shared.b16 {%0,%1,%2,%3}, [%4];" \
                 : "=r"(r0), "=r"(r1), "=r"(r2), "=r"(r3) : "r"(addr))

__device__ __forceinline__ void mma16816(float* d, const uint32_t* a,
                                         uint32_t b0, uint32_t b1) {
    asm volatile("mma.sync.aligned.m16n8k16.row.col.f32.f16.f16.f32 "
                 "{%0,%1,%2,%3}, {%4,%5,%6,%7}, {%8,%9}, {%0,%1,%2,%3};"
                 : "+f"(d[0]), "+f"(d[1]), "+f"(d[2]), "+f"(d[3])
                 : "r"(a[0]), "r"(a[1]), "r"(a[2]), "r"(a[3]), "r"(b0), "r"(b1));
}

// ---------------- kernel 1: L2 normalize (blocks 0..2047) + W prep (blocks 2048..2079) ----------------
__global__ __launch_bounds__(256) void k_prep(const float* __restrict__ t,
                                              const float* __restrict__ d,
                                              const float* __restrict__ W1) {
    __shared__ float sh[64][65];
    const int tid = threadIdx.x;
    if (blockIdx.x < 2048) {
        int row = blockIdx.x;
        const float* src;
        float* dst;
        if (row < B_ * N_) { src = t + row * E_;            dst = g_tn + row * E_; }
        else               { int r = row - B_ * N_;
                             src = d + r * E_;              dst = g_dn + r * E_; }
        float x = src[tid];
        float s = x * x;
        #pragma unroll
        for (int o = 16; o > 0; o >>= 1) s += __shfl_xor_sync(0xffffffffu, s, o);
        if ((tid & 31) == 0) sh[0][tid >> 5] = s;
        __syncthreads();
        float tot = 0.f;
        #pragma unroll
        for (int i = 0; i < 8; i++) tot += sh[0][i];
        float inv = 1.f / fmaxf(sqrtf(tot), 1e-12f);
        dst[tid] = x * inv;
    } else {
        // W1c^T -> single fp16, swizzled. blk -> (c: 64-k chunk of 4, hb: 64-h block of 8)
        const int blk = blockIdx.x - 2048;
        const int c = blk & 3, hb = blk >> 2;
        {
            int kk0 = tid >> 6, hl = tid & 63;
            #pragma unroll
            for (int it = 0; it < 16; it++) {
                int k = kk0 + it * 4;
                sh[k][hl] = W1[(2 * E_ + c * 64 + k) * H_ + hb * 64 + hl];
            }
        }
        __syncthreads();
        const int hl = tid >> 2, jj = tid & 3;   // h row, 16-k slice
        const int h = hb * 64 + hl;
        #pragma unroll
        for (int s = 0; s < 2; s++) {
            uint32_t w_[4];
            #pragma unroll
            for (int i = 0; i < 4; i++) {
                int k = jj * 16 + s * 8 + i * 2;
                w_[i] = pk2h(__float2half(sh[k][hl]), __float2half(sh[k + 1][hl]));
            }
            *(uint4*)(g_W + c * 65536 + SWZ(h * 128 + jj * 32 + s * 16)) =
                make_uint4(w_[0], w_[1], w_[2], w_[3]);
        }
    }
}

// ---------------- kernel 2: A = t@W1a + b1 ; Bv = d@W1b ----------------
__global__ __launch_bounds__(256) void k_ab(const float* __restrict__ W1,
                                            const float* __restrict__ b1) {
    const int z    = blockIdx.y;
    const int row0 = blockIdx.x * 16;
    const float* X = z ? g_dn : g_tn;
    float*       O = z ? g_Bv : g_A;
    const float* W = W1 + z * (E_ * H_);

    __shared__ float xs[16][17];
    __shared__ float wc[16][H_];

    const int tid = threadIdx.x, w = tid >> 5, l = tid & 31;
    float acc[2][16];
    #pragma unroll
    for (int r = 0; r < 2; r++)
        #pragma unroll
        for (int j = 0; j < 16; j++) acc[r][j] = 0.f;

    for (int c = 0; c < 16; c++) {
        __syncthreads();
        {
            int kk = tid >> 4, r = tid & 15;
            xs[kk][r] = X[(row0 + r) * E_ + c * 16 + kk];
        }
        {
            const float4* src = (const float4*)(W + c * 16 * H_);
            float4* dstp = (float4*)&wc[0][0];
            #pragma unroll
            for (int u = 0; u < 8; u++) dstp[tid + 256 * u] = src[tid + 256 * u];
        }
        __syncthreads();
        #pragma unroll 4
        for (int kk = 0; kk < 16; kk++) {
            float a0 = xs[kk][w * 2 + 0];
            float a1 = xs[kk][w * 2 + 1];
            #pragma unroll
            for (int j = 0; j < 16; j++) {
                float bv = wc[kk][l + 32 * j];
                acc[0][j] = fmaf(a0, bv, acc[0][j]);
                acc[1][j] = fmaf(a1, bv, acc[1][j]);
            }
        }
    }
    #pragma unroll
    for (int r = 0; r < 2; r++) {
        int row = row0 + w * 2 + r;
        #pragma unroll
        for (int j = 0; j < 16; j++) {
            int h = l + 32 * j;
            float v = acc[r][j] + (z == 0 ? b1[h] : 0.f);
            O[row * H_ + h] = v;
        }
    }
}

// ---------------- kernel 3: fp16 2-pass mma.sync GEMM + fused epilogue ----------------
// CTA = (b, n, m-half): 64 pairs x 512 H, 512 threads / 16 warps.
// Warp tile: mw = wid>>3 (32 m), hq = wid&7 (64 h). K = 4 chunks of 64.
// A split fp16 hi/lo (built on the fly), W single fp16 (preprocessed).
enum {
    OFF_W    = 0,        // 2 x 64KB  W chunk double buffer
    OFF_A    = 131072,   // 2 x 16KB  A chunk double buffer (hi 8KB | lo 8KB)
    OFF_TS   = 163840,   // 1KB  t row
    OFF_AS   = 164864,   // 2KB  A row
    OFF_GAM  = 166912,   // 2KB
    OFF_BET  = 168960,   // 2KB
    OFF_W2   = 171008,   // 2KB
    OFF_RED1 = 173056,   // 2KB  [8 hq][64 m]
    OFF_RED2 = 175104,   // 2KB
    SMEM_SZ  = 177152
};

__global__ void __launch_bounds__(512, 1) k_main(const float* __restrict__ gamma,
                                                 const float* __restrict__ beta,
                                                 const float* __restrict__ W2,
                                                 const float* __restrict__ b2,
                                                 float* __restrict__ out) {
    extern __shared__ __align__(16) char smem[];
    const uint32_t sbase = smem_u32(smem);
    const int tid = threadIdx.x, wid = tid >> 5, lid = tid & 31;
    const int b = blockIdx.z, n = blockIdx.y, m0 = blockIdx.x * 64;
    const int mw = wid >> 3, hq = wid & 7;

    float* ts   = (float*)(smem + OFF_TS);
    float* as_  = (float*)(smem + OFF_AS);
    float* gam  = (float*)(smem + OFF_GAM);
    float* bet  = (float*)(smem + OFF_BET);
    float* w2s  = (float*)(smem + OFF_W2);
    float* red1 = (float*)(smem + OFF_RED1);
    float* red2 = (float*)(smem + OFF_RED2);

    if (tid < 256) ts[tid] = g_tn[(b * N_ + n) * E_ + tid];
    {
        int h = tid;
        as_[h] = g_A[(b * N_ + n) * H_ + h];
        gam[h] = gamma[h];
        bet[h] = beta[h];
        w2s[h] = W2[h];
    }

    // ---- chunk loaders ----
    const int am = tid >> 3, aj = tid & 7;   // A-build: m row (64), 8-k slice (8)
    const float* drowA = g_dn + (b * M_ + m0 + am) * E_;
    const uint32_t a_sw = SWZ((uint32_t)(am * 128 + aj * 16));

    auto storeA = [&](int c, int buf, float4 dv0, float4 dv1) {
        const float* tp = ts + c * 64 + aj * 8;
        float x[8];
        x[0] = fabsf(tp[0] - dv0.x); x[1] = fabsf(tp[1] - dv0.y);
        x[2] = fabsf(tp[2] - dv0.z); x[3] = fabsf(tp[3] - dv0.w);
        x[4] = fabsf(tp[4] - dv1.x); x[5] = fabsf(tp[5] - dv1.y);
        x[6] = fabsf(tp[6] - dv1.z); x[7] = fabsf(tp[7] - dv1.w);
        uint32_t hi[4], lo[4];
        #pragma unroll
        for (int i = 0; i < 4; i++) {
            __half h0 = __float2half(x[2 * i + 0]);
            __half h1 = __float2half(x[2 * i + 1]);
            __half l0 = __float2half(x[2 * i + 0] - __half2float(h0));
            __half l1 = __float2half(x[2 * i + 1] - __half2float(h1));
            hi[i] = pk2h(h0, h1);
            lo[i] = pk2h(l0, l1);
        }
        char* abuf = smem + OFF_A + buf * 16384;
        *(uint4*)(abuf + a_sw)        = make_uint4(hi[0], hi[1], hi[2], hi[3]);
        *(uint4*)(abuf + 8192 + a_sw) = make_uint4(lo[0], lo[1], lo[2], lo[3]);
    };
    auto loadW = [&](int c, int buf) {
        const char* src = (const char*)g_W + c * 65536 + tid * 16;
        uint32_t dst = sbase + OFF_W + buf * 65536 + tid * 16;
        #pragma unroll
        for (int u = 0; u < 8; u++)
            CP_ASYNC16(dst + u * 8192, src + u * 8192);
    };

    // ---- accumulators + ldmatrix addressing ----
    float acc[2][8][4];
    #pragma unroll
    for (int mt = 0; mt < 2; mt++)
        #pragma unroll
        for (int nt = 0; nt < 8; nt++)
            #pragma unroll
            for (int r = 0; r < 4; r++) acc[mt][nt][r] = 0.f;

    // A: lanes 0-7 (m0-7,klo), 8-15 (m8-15,klo), 16-23 (m0-7,khi), 24-31 (m8-15,khi)
    const uint32_t arowoff = (uint32_t)(mw * 32 + (lid & 15)) * 128;
    const uint32_t asel    = (uint32_t)(lid >> 4) * 16;
    // B: lanes 0-7 (n0-7,klo), 8-15 (n0-7,khi), 16-23 (n8-15,klo), 24-31 (n8-15,khi)
    const uint32_t browoff = (uint32_t)(hq * 64 + (lid & 7) + ((lid >> 4) << 3)) * 128;
    const uint32_t bsel    = (uint32_t)((lid >> 3) & 1) * 16;
    const uint32_t xr      = (uint32_t)(lid & 7) << 4;

    auto gemm = [&](int buf) {
        const uint32_t aBase = sbase + OFF_A + buf * 16384 + arowoff;
        const uint32_t bBase = sbase + OFF_W + buf * 65536 + browoff;
        #pragma unroll
        for (int ks = 0; ks < 4; ks++) {
            const uint32_t ao = (ks * 32 + asel) ^ xr;
            const uint32_t bo = (ks * 32 + bsel) ^ xr;
            uint32_t ah[2][4], al[2][4];
            #pragma unroll
            for (int mt = 0; mt < 2; mt++) {
                LDMX4(ah[mt][0], ah[mt][1], ah[mt][2], ah[mt][3], aBase + mt * 2048 + ao);
                LDMX4(al[mt][0], al[mt][1], al[mt][2], al[mt][3], aBase + 8192 + mt * 2048 + ao);
            }
            #pragma unroll
            for (int np = 0; np < 4; np++) {
                uint32_t bf[4];
                LDMX4(bf[0], bf[1], bf[2], bf[3], bBase + np * 2048 + bo);
                const int nt = np * 2;
                #pragma unroll
                for (int mt = 0; mt < 2; mt++) {
                    mma16816(acc[mt][nt + 0], ah[mt], bf[0], bf[1]);
                    mma16816(acc[mt][nt + 1], ah[mt], bf[2], bf[3]);
                    mma16816(acc[mt][nt + 0], al[mt], bf[0], bf[1]);
                    mma16816(acc[mt][nt + 1], al[mt], bf[2], bf[3]);
                }
            }
        }
    };

    // ---- software-pipelined K loop (4 chunks of 64) ----
    float4 pf0, pf1;
    pf0 = *(const float4*)(drowA + aj * 8);
    pf1 = *(const float4*)(drowA + aj * 8 + 4);
    loadW(0, 0);
    CP_COMMIT();
    __syncthreads();            // ts ready (also orders initial smem fills)
    storeA(0, 0, pf0, pf1);
    CP_WAIT0();
    __syncthreads();
    #pragma unroll
    for (int c = 0; c < 4; c++) {
        const int buf = c & 1;
        if (c < 3) {
            loadW(c + 1, buf ^ 1);
            CP_COMMIT();
            pf0 = *(const float4*)(drowA + (c + 1) * 64 + aj * 8);       // LDG issued early,
            pf1 = *(const float4*)(drowA + (c + 1) * 64 + aj * 8 + 4);   // consumed after gemm
        }
        gemm(buf);
        if (c < 3) {
            storeA(c + 1, buf ^ 1, pf0, pf1);
            CP_WAIT0();
        }
        __syncthreads();
    }

    // ---- fused epilogue ----
    const float b2v = b2[0];
    float s1[2][2] = {{0.f, 0.f}, {0.f, 0.f}};
    float s2[2][2] = {{0.f, 0.f}, {0.f, 0.f}};
    const int mbase = m0 + mw * 32;
    #pragma unroll
    for (int mt = 0; mt < 2; mt++) {
        #pragma unroll
        for (int half = 0; half < 2; half++) {
            const int mr = mt * 16 + (lid >> 2) + half * 8;
            const float* bp = g_Bv + (b * M_ + mbase + mr) * H_ + hq * 64 + (lid & 3) * 2;
            #pragma unroll
            for (int nt = 0; nt < 8; nt++) {
                float2 bv = *(const float2*)(bp + nt * 8);
                int h = hq * 64 + nt * 8 + (lid & 3) * 2;
                float v0 = acc[mt][nt][half * 2 + 0] + as_[h + 0] + bv.x;
                float v1 = acc[mt][nt][half * 2 + 1] + as_[h + 1] + bv.y;
                acc[mt][nt][half * 2 + 0] = v0;
                acc[mt][nt][half * 2 + 1] = v1;
                s1[mt][half] += v0 + v1;
                s2[mt][half] = fmaf(v0, v0, fmaf(v1, v1, s2[mt][half]));
            }
        }
    }
    #pragma unroll
    for (int mt = 0; mt < 2; mt++)
        #pragma unroll
        for (int half = 0; half < 2; half++)
            #pragma unroll
            for (int o = 1; o <= 2; o <<= 1) {
                s1[mt][half] += __shfl_xor_sync(0xffffffffu, s1[mt][half], o);
                s2[mt][half] += __shfl_xor_sync(0xffffffffu, s2[mt][half], o);
            }
    if ((lid & 3) == 0) {
        #pragma unroll
        for (int mt = 0; mt < 2; mt++)
            #pragma unroll
            for (int half = 0; half < 2; half++) {
                int m = mw * 32 + mt * 16 + (lid >> 2) + half * 8;
                red1[hq * 64 + m] = s1[mt][half];
                red2[hq * 64 + m] = s2[mt][half];
            }
    }
    __syncthreads();
    float mu[2][2], inv[2][2];
    #pragma unroll
    for (int mt = 0; mt < 2; mt++)
        #pragma unroll
        for (int half = 0; half < 2; half++) {
            int m = mw * 32 + mt * 16 + (lid >> 2) + half * 8;
            float S1 = 0.f, S2 = 0.f;
            #pragma unroll
            for (int q = 0; q < 8; q++) {
                S1 += red1[q * 64 + m];
                S2 += red2[q * 64 + m];
            }
            float mm = S1 * (1.f / 512.f);
            mu[mt][half]  = mm;
            inv[mt][half] = rsqrtf(fmaxf(S2 * (1.f / 512.f) - mm * mm, 0.f) + 1e-5f);
        }
    __syncthreads();

    float o_[2][2] = {{0.f, 0.f}, {0.f, 0.f}};
    #pragma unroll
    for (int mt = 0; mt < 2; mt++) {
        #pragma unroll
        for (int half = 0; half < 2; half++) {
            float mm = mu[mt][half], iv = inv[mt][half];
            #pragma unroll
            for (int nt = 0; nt < 8; nt++) {
                int h = hq * 64 + nt * 8 + (lid & 3) * 2;
                #pragma unroll
                for (int e = 0; e < 2; e++) {
                    float v = acc[mt][nt][half * 2 + e];
                    float x = fmaf((v - mm) * iv, gam[h + e], bet[h + e]);
                    float sg = 1.f / (1.f + __expf(-x));
                    o_[mt][half] = fmaf(x * sg, w2s[h + e], o_[mt][half]);
                }
            }
        }
    }
    #pragma unroll
    for (int mt = 0; mt < 2; mt++)
        #pragma unroll
        for (int half = 0; half < 2; half++)
            #pragma unroll
            for (int o = 1; o <= 2; o <<= 1)
                o_[mt][half] += __shfl_xor_sync(0xffffffffu, o_[mt][half], o);
    if ((lid & 3) == 0) {
        #pragma unroll
        for (int mt = 0; mt < 2; mt++)
            #pragma unroll
            for (int half = 0; half < 2; half++) {
                int m = mw * 32 + mt * 16 + (lid >> 2) + half * 8;
                red1[hq * 64 + m] = o_[mt][half];
            }
    }
    __syncthreads();
    if (tid < 64) {
        int m = tid;
        float oo = b2v;
        #pragma unroll
        for (int q = 0; q < 8; q++) oo += red1[q * 64 + m];
        out[(b * N_ + n) * M_ + m0 + m] = oo;
    }
}

// ---------------- launch ----------------
extern "C" void kernel_launch(void* const* d_in, const int* in_sizes, int n_in,
                              void* d_out, int out_size) {
    const float* t     = (const float*)d_in[0];
    const float* d     = (const float*)d_in[1];
    const float* W1    = (const float*)d_in[2];
    const float* b1    = (const float*)d_in[3];
    const float* gamma = (const float*)d_in[4];
    const float* beta  = (const float*)d_in[5];
    const float* W2    = (const float*)d_in[6];
    const float* b2    = (const float*)d_in[7];
    float* out = (float*)d_out;

    cudaFuncSetAttribute(k_main, cudaFuncAttributeMaxDynamicSharedMemorySize, SMEM_SZ);

    k_prep<<<2048 + 32, 256>>>(t, d, W1);
    k_ab<<<dim3(64, 2), 256>>>(W1, b1);
    k_main<<<dim3(2, N_, B_), 512, SMEM_SZ>>>(gamma, beta, W2, b2, out);
}

// round 12
// speedup vs baseline: 1.0011x; 1.0011x over previous
#include <cuda_runtime.h>
#include <cuda_bf16.h>
#include <cuda_fp16.h>
#include <stdint.h>
#include <math.h>

#define B_ 8
#define N_ 128
#define M_ 128
#define E_ 256
#define H_ 512

// ---------------- scratch (no allocations allowed) ----------------
__device__ float g_tn[B_ * N_ * E_];   // l2-normalized track features
__device__ float g_dn[B_ * M_ * E_];   // l2-normalized det features
__device__ float g_A [B_ * N_ * H_];   // t_n @ W1[0:E]   + b1
__device__ float g_Bv[B_ * M_ * H_];   // d_m @ W1[E:2E]
// W1c^T single fp16: per 64-k chunk, 512 rows (h) x 128B (64 fp16 k), swizzled
__device__ __align__(16) unsigned char g_W[4 * 65536];

// XOR bits[4:6] of the 128B row offset with (row & 7)
#define SWZ(o) ((o) ^ (((o) >> 3) & 0x70))

__device__ __forceinline__ uint32_t smem_u32(const void* p) {
    uint32_t a;
    asm("{ .reg .u64 t; cvta.to.shared.u64 t, %1; cvt.u32.u64 %0, t; }" : "=r"(a) : "l"(p));
    return a;
}
__device__ __forceinline__ uint32_t pk2h(__half a, __half b) {
    return (uint32_t)__half_as_ushort(a) | ((uint32_t)__half_as_ushort(b) << 16);
}
#define CP_ASYNC16(dst, src) \
    asm volatile("cp.async.cg.shared.global [%0], [%1], 16;" :: "r"(dst), "l"(src) : "memory")
#define CP_COMMIT() asm volatile("cp.async.commit_group;" ::: "memory")
#define CP_WAIT0()  asm volatile("cp.async.wait_group 0;" ::: "memory")

#define LDMX4(r0, r1, r2, r3, addr) \
    asm volatile("ldmatrix.sync.aligned.m8n8.x4.shared.b16 {%0,%1,%2,%3}, [%4];" \
                 : "=r"(r0), "=r"(r1), "=r"(r2), "=r"(r3) : "r"(addr))

__device__ __forceinline__ void mma16816(float* d, const uint32_t* a,
                                         uint32_t b0, uint32_t b1) {
    asm volatile("mma.sync.aligned.m16n8k16.row.col.f32.f16.f16.f32 "
                 "{%0,%1,%2,%3}, {%4,%5,%6,%7}, {%8,%9}, {%0,%1,%2,%3};"
                 : "+f"(d[0]), "+f"(d[1]), "+f"(d[2]), "+f"(d[3])
                 : "r"(a[0]), "r"(a[1]), "r"(a[2]), "r"(a[3]), "r"(b0), "r"(b1));
}

// ---------------- kernel 1: L2 normalize (blocks 0..2047) + W prep (blocks 2048..2079) ----------------
__global__ __launch_bounds__(256) void k_prep(const float* __restrict__ t,
                                              const float* __restrict__ d,
                                              const float* __restrict__ W1) {
    __shared__ float sh[64][65];
    const int tid = threadIdx.x;
    if (blockIdx.x < 2048) {
        int row = blockIdx.x;
        const float* src;
        float* dst;
        if (row < B_ * N_) { src = t + row * E_;            dst = g_tn + row * E_; }
        else               { int r = row - B_ * N_;
                             src = d + r * E_;              dst = g_dn + r * E_; }
        float x = src[tid];
        float s = x * x;
        #pragma unroll
        for (int o = 16; o > 0; o >>= 1) s += __shfl_xor_sync(0xffffffffu, s, o);
        if ((tid & 31) == 0) sh[0][tid >> 5] = s;
        __syncthreads();
        float tot = 0.f;
        #pragma unroll
        for (int i = 0; i < 8; i++) tot += sh[0][i];
        float inv = 1.f / fmaxf(sqrtf(tot), 1e-12f);
        dst[tid] = x * inv;
    } else {
        // W1c^T -> single fp16, swizzled. blk -> (c: 64-k chunk of 4, hb: 64-h block of 8)
        const int blk = blockIdx.x - 2048;
        const int c = blk & 3, hb = blk >> 2;
        {
            int kk0 = tid >> 6, hl = tid & 63;
            #pragma unroll
            for (int it = 0; it < 16; it++) {
                int k = kk0 + it * 4;
                sh[k][hl] = W1[(2 * E_ + c * 64 + k) * H_ + hb * 64 + hl];
            }
        }
        __syncthreads();
        const int hl = tid >> 2, jj = tid & 3;   // h row, 16-k slice
        const int h = hb * 64 + hl;
        #pragma unroll
        for (int s = 0; s < 2; s++) {
            uint32_t w_[4];
            #pragma unroll
            for (int i = 0; i < 4; i++) {
                int k = jj * 16 + s * 8 + i * 2;
                w_[i] = pk2h(__float2half(sh[k][hl]), __float2half(sh[k + 1][hl]));
            }
            *(uint4*)(g_W + c * 65536 + SWZ(h * 128 + jj * 32 + s * 16)) =
                make_uint4(w_[0], w_[1], w_[2], w_[3]);
        }
    }
}

// ---------------- kernel 2: A = t@W1a + b1 ; Bv = d@W1b ----------------
__global__ __launch_bounds__(256) void k_ab(const float* __restrict__ W1,
                                            const float* __restrict__ b1) {
    const int z    = blockIdx.y;
    const int row0 = blockIdx.x * 16;
    const float* X = z ? g_dn : g_tn;
    float*       O = z ? g_Bv : g_A;
    const float* W = W1 + z * (E_ * H_);

    __shared__ float xs[16][17];
    __shared__ float wc[16][H_];

    const int tid = threadIdx.x, w = tid >> 5, l = tid & 31;
    float acc[2][16];
    #pragma unroll
    for (int r = 0; r < 2; r++)
        #pragma unroll
        for (int j = 0; j < 16; j++) acc[r][j] = 0.f;

    for (int c = 0; c < 16; c++) {
        __syncthreads();
        {
            int kk = tid >> 4, r = tid & 15;
            xs[kk][r] = X[(row0 + r) * E_ + c * 16 + kk];
        }
        {
            const float4* src = (const float4*)(W + c * 16 * H_);
            float4* dstp = (float4*)&wc[0][0];
            #pragma unroll
            for (int u = 0; u < 8; u++) dstp[tid + 256 * u] = src[tid + 256 * u];
        }
        __syncthreads();
        #pragma unroll 4
        for (int kk = 0; kk < 16; kk++) {
            float a0 = xs[kk][w * 2 + 0];
            float a1 = xs[kk][w * 2 + 1];
            #pragma unroll
            for (int j = 0; j < 16; j++) {
                float bv = wc[kk][l + 32 * j];
                acc[0][j] = fmaf(a0, bv, acc[0][j]);
                acc[1][j] = fmaf(a1, bv, acc[1][j]);
            }
        }
    }
    #pragma unroll
    for (int r = 0; r < 2; r++) {
        int row = row0 + w * 2 + r;
        #pragma unroll
        for (int j = 0; j < 16; j++) {
            int h = l + 32 * j;
            float v = acc[r][j] + (z == 0 ? b1[h] : 0.f);
            O[row * H_ + h] = v;
        }
    }
}

// ---------------- kernel 3: fp16 2-pass mma.sync GEMM + fused epilogue ----------------
// CTA = (b, n, m-half): 64 pairs x 512 H, 512 threads / 16 warps.
// Warp tile: mw = wid>>3 (32 m), hq = wid&7 (64 h). K = 4 chunks of 64.
// A split fp16 hi/lo (built on the fly), W single fp16 (preprocessed).
enum {
    OFF_W    = 0,        // 2 x 64KB  W chunk double buffer
    OFF_A    = 131072,   // 2 x 16KB  A chunk double buffer (hi 8KB | lo 8KB)
    OFF_TS   = 163840,   // 1KB  t row
    OFF_AS   = 164864,   // 2KB  A row
    OFF_GAM  = 166912,   // 2KB
    OFF_BET  = 168960,   // 2KB
    OFF_W2   = 171008,   // 2KB
    OFF_RED1 = 173056,   // 2KB  [8 hq][64 m]
    OFF_RED2 = 175104,   // 2KB
    SMEM_SZ  = 177152
};

__global__ void __launch_bounds__(512, 1) k_main(const float* __restrict__ gamma,
                                                 const float* __restrict__ beta,
                                                 const float* __restrict__ W2,
                                                 const float* __restrict__ b2,
                                                 float* __restrict__ out) {
    extern __shared__ __align__(16) char smem[];
    const uint32_t sbase = smem_u32(smem);
    const int tid = threadIdx.x, wid = tid >> 5, lid = tid & 31;
    const int b = blockIdx.z, n = blockIdx.y, m0 = blockIdx.x * 64;
    const int mw = wid >> 3, hq = wid & 7;

    float* ts   = (float*)(smem + OFF_TS);
    float* as_  = (float*)(smem + OFF_AS);
    float* gam  = (float*)(smem + OFF_GAM);
    float* bet  = (float*)(smem + OFF_BET);
    float* w2s  = (float*)(smem + OFF_W2);
    float* red1 = (float*)(smem + OFF_RED1);
    float* red2 = (float*)(smem + OFF_RED2);

    if (tid < 256) ts[tid] = g_tn[(b * N_ + n) * E_ + tid];
    {
        int h = tid;
        as_[h] = g_A[(b * N_ + n) * H_ + h];
        gam[h] = gamma[h];
        bet[h] = beta[h];
        w2s[h] = W2[h];
    }

    // ---- chunk loaders ----
    const int am = tid >> 3, aj = tid & 7;   // A-build: m row (64), 8-k slice (8)
    const float* drowA = g_dn + (b * M_ + m0 + am) * E_;
    const uint32_t a_sw = SWZ((uint32_t)(am * 128 + aj * 16));

    auto storeA = [&](int c, int buf, float4 dv0, float4 dv1) {
        const float* tp = ts + c * 64 + aj * 8;
        float x[8];
        x[0] = fabsf(tp[0] - dv0.x); x[1] = fabsf(tp[1] - dv0.y);
        x[2] = fabsf(tp[2] - dv0.z); x[3] = fabsf(tp[3] - dv0.w);
        x[4] = fabsf(tp[4] - dv1.x); x[5] = fabsf(tp[5] - dv1.y);
        x[6] = fabsf(tp[6] - dv1.z); x[7] = fabsf(tp[7] - dv1.w);
        uint32_t hi[4], lo[4];
        #pragma unroll
        for (int i = 0; i < 4; i++) {
            __half h0 = __float2half(x[2 * i + 0]);
            __half h1 = __float2half(x[2 * i + 1]);
            __half l0 = __float2half(x[2 * i + 0] - __half2float(h0));
            __half l1 = __float2half(x[2 * i + 1] - __half2float(h1));
            hi[i] = pk2h(h0, h1);
            lo[i] = pk2h(l0, l1);
        }
        char* abuf = smem + OFF_A + buf * 16384;
        *(uint4*)(abuf + a_sw)        = make_uint4(hi[0], hi[1], hi[2], hi[3]);
        *(uint4*)(abuf + 8192 + a_sw) = make_uint4(lo[0], lo[1], lo[2], lo[3]);
    };
    auto loadW = [&](int c, int buf) {
        const char* src = (const char*)g_W + c * 65536 + tid * 16;
        uint32_t dst = sbase + OFF_W + buf * 65536 + tid * 16;
        #pragma unroll
        for (int u = 0; u < 8; u++)
            CP_ASYNC16(dst + u * 8192, src + u * 8192);
    };

    // ---- accumulators + ldmatrix addressing ----
    float acc[2][8][4];
    #pragma unroll
    for (int mt = 0; mt < 2; mt++)
        #pragma unroll
        for (int nt = 0; nt < 8; nt++)
            #pragma unroll
            for (int r = 0; r < 4; r++) acc[mt][nt][r] = 0.f;

    // A: lanes 0-7 (m0-7,klo), 8-15 (m8-15,klo), 16-23 (m0-7,khi), 24-31 (m8-15,khi)
    const uint32_t arowoff = (uint32_t)(mw * 32 + (lid & 15)) * 128;
    const uint32_t asel    = (uint32_t)(lid >> 4) * 16;
    // B: lanes 0-7 (n0-7,klo), 8-15 (n0-7,khi), 16-23 (n8-15,klo), 24-31 (n8-15,khi)
    const uint32_t browoff = (uint32_t)(hq * 64 + (lid & 7) + ((lid >> 4) << 3)) * 128;
    const uint32_t bsel    = (uint32_t)((lid >> 3) & 1) * 16;
    const uint32_t xr      = (uint32_t)(lid & 7) << 4;

    auto gemm = [&](int buf) {
        const uint32_t aBase = sbase + OFF_A + buf * 16384 + arowoff;
        const uint32_t bBase = sbase + OFF_W + buf * 65536 + browoff;
        #pragma unroll
        for (int ks = 0; ks < 4; ks++) {
            const uint32_t ao = (ks * 32 + asel) ^ xr;
            const uint32_t bo = (ks * 32 + bsel) ^ xr;
            uint32_t ah[2][4], al[2][4];
            #pragma unroll
            for (int mt = 0; mt < 2; mt++) {
                LDMX4(ah[mt][0], ah[mt][1], ah[mt][2], ah[mt][3], aBase + mt * 2048 + ao);
                LDMX4(al[mt][0], al[mt][1], al[mt][2], al[mt][3], aBase + 8192 + mt * 2048 + ao);
            }
            #pragma unroll
            for (int np = 0; np < 4; np++) {
                uint32_t bf[4];
                LDMX4(bf[0], bf[1], bf[2], bf[3], bBase + np * 2048 + bo);
                const int nt = np * 2;
                #pragma unroll
                for (int mt = 0; mt < 2; mt++) {
                    mma16816(acc[mt][nt + 0], ah[mt], bf[0], bf[1]);
                    mma16816(acc[mt][nt + 1], ah[mt], bf[2], bf[3]);
                    mma16816(acc[mt][nt + 0], al[mt], bf[0], bf[1]);
                    mma16816(acc[mt][nt + 1], al[mt], bf[2], bf[3]);
                }
            }
        }
    };

    // ---- software-pipelined K loop (4 chunks of 64) ----
    float4 pf0, pf1;
    pf0 = *(const float4*)(drowA + aj * 8);
    pf1 = *(const float4*)(drowA + aj * 8 + 4);
    loadW(0, 0);
    CP_COMMIT();
    __syncthreads();            // ts ready (also orders initial smem fills)
    storeA(0, 0, pf0, pf1);
    CP_WAIT0();
    __syncthreads();
    #pragma unroll
    for (int c = 0; c < 4; c++) {
        const int buf = c & 1;
        if (c < 3) {
            loadW(c + 1, buf ^ 1);
            CP_COMMIT();
            pf0 = *(const float4*)(drowA + (c + 1) * 64 + aj * 8);       // LDG issued early,
            pf1 = *(const float4*)(drowA + (c + 1) * 64 + aj * 8 + 4);   // consumed after gemm
        }
        gemm(buf);
        if (c < 3) {
            storeA(c + 1, buf ^ 1, pf0, pf1);
            CP_WAIT0();
        }
        __syncthreads();
    }

    // ---- fused epilogue ----
    const float b2v = b2[0];
    float s1[2][2] = {{0.f, 0.f}, {0.f, 0.f}};
    float s2[2][2] = {{0.f, 0.f}, {0.f, 0.f}};
    const int mbase = m0 + mw * 32;
    #pragma unroll
    for (int mt = 0; mt < 2; mt++) {
        #pragma unroll
        for (int half = 0; half < 2; half++) {
            const int mr = mt * 16 + (lid >> 2) + half * 8;
            const float* bp = g_Bv + (b * M_ + mbase + mr) * H_ + hq * 64 + (lid & 3) * 2;
            #pragma unroll
            for (int nt = 0; nt < 8; nt++) {
                float2 bv = *(const float2*)(bp + nt * 8);
                int h = hq * 64 + nt * 8 + (lid & 3) * 2;
                float v0 = acc[mt][nt][half * 2 + 0] + as_[h + 0] + bv.x;
                float v1 = acc[mt][nt][half * 2 + 1] + as_[h + 1] + bv.y;
                acc[mt][nt][half * 2 + 0] = v0;
                acc[mt][nt][half * 2 + 1] = v1;
                s1[mt][half] += v0 + v1;
                s2[mt][half] = fmaf(v0, v0, fmaf(v1, v1, s2[mt][half]));
            }
        }
    }
    #pragma unroll
    for (int mt = 0; mt < 2; mt++)
        #pragma unroll
        for (int half = 0; half < 2; half++)
            #pragma unroll
            for (int o = 1; o <= 2; o <<= 1) {
                s1[mt][half] += __shfl_xor_sync(0xffffffffu, s1[mt][half], o);
                s2[mt][half] += __shfl_xor_sync(0xffffffffu, s2[mt][half], o);
            }
    if ((lid & 3) == 0) {
        #pragma unroll
        for (int mt = 0; mt < 2; mt++)
            #pragma unroll
            for (int half = 0; half < 2; half++) {
                int m = mw * 32 + mt * 16 + (lid >> 2) + half * 8;
                red1[hq * 64 + m] = s1[mt][half];
                red2[hq * 64 + m] = s2[mt][half];
            }
    }
    __syncthreads();
    float mu[2][2], inv[2][2];
    #pragma unroll
    for (int mt = 0; mt < 2; mt++)
        #pragma unroll
        for (int half = 0; half < 2; half++) {
            int m = mw * 32 + mt * 16 + (lid >> 2) + half * 8;
            float S1 = 0.f, S2 = 0.f;
            #pragma unroll
            for (int q = 0; q < 8; q++) {
                S1 += red1[q * 64 + m];
                S2 += red2[q * 64 + m];
            }
            float mm = S1 * (1.f / 512.f);
            mu[mt][half]  = mm;
            inv[mt][half] = rsqrtf(fmaxf(S2 * (1.f / 512.f) - mm * mm, 0.f) + 1e-5f);
        }
    __syncthreads();

    float o_[2][2] = {{0.f, 0.f}, {0.f, 0.f}};
    #pragma unroll
    for (int mt = 0; mt < 2; mt++) {
        #pragma unroll
        for (int half = 0; half < 2; half++) {
            float mm = mu[mt][half], iv = inv[mt][half];
            #pragma unroll
            for (int nt = 0; nt < 8; nt++) {
                int h = hq * 64 + nt * 8 + (lid & 3) * 2;
                #pragma unroll
                for (int e = 0; e < 2; e++) {
                    float v = acc[mt][nt][half * 2 + e];
                    float x = fmaf((v - mm) * iv, gam[h + e], bet[h + e]);
                    float sg = 1.f / (1.f + __expf(-x));
                    o_[mt][half] = fmaf(x * sg, w2s[h + e], o_[mt][half]);
                }
            }
        }
    }
    #pragma unroll
    for (int mt = 0; mt < 2; mt++)
        #pragma unroll
        for (int half = 0; half < 2; half++)
            #pragma unroll
            for (int o = 1; o <= 2; o <<= 1)
                o_[mt][half] += __shfl_xor_sync(0xffffffffu, o_[mt][half], o);
    if ((lid & 3) == 0) {
        #pragma unroll
        for (int mt = 0; mt < 2; mt++)
            #pragma unroll
            for (int half = 0; half < 2; half++) {
                int m = mw * 32 + mt * 16 + (lid >> 2) + half * 8;
                red1[hq * 64 + m] = o_[mt][half];
            }
    }
    __syncthreads();
    if (tid < 64) {
        int m = tid;
        float oo = b2v;
        #pragma unroll
        for (int q = 0; q < 8; q++) oo += red1[q * 64 + m];
        out[(b * N_ + n) * M_ + m0 + m] = oo;
    }
}

// ---------------- launch ----------------
extern "C" void kernel_launch(void* const* d_in, const int* in_sizes, int n_in,
                              void* d_out, int out_size) {
    const float* t     = (const float*)d_in[0];
    const float* d     = (const float*)d_in[1];
    const float* W1    = (const float*)d_in[2];
    const float* b1    = (const float*)d_in[3];
    const float* gamma = (const float*)d_in[4];
    const float* beta  = (const float*)d_in[5];
    const float* W2    = (const float*)d_in[6];
    const float* b2    = (const float*)d_in[7];
    float* out = (float*)d_out;

    cudaFuncSetAttribute(k_main, cudaFuncAttributeMaxDynamicSharedMemorySize, SMEM_SZ);

    k_prep<<<2048 + 32, 256>>>(t, d, W1);
    k_ab<<<dim3(64, 2), 256>>>(W1, b1);
    k_main<<<dim3(2, N_, B_), 512, SMEM_SZ>>>(gamma, beta, W2, b2, out);
}

// round 13
// speedup vs baseline: 1.0017x; 1.0006x over previous
#include <cuda_runtime.h>
#include <cuda_bf16.h>
#include <cuda_fp16.h>
#include <stdint.h>
#include <math.h>

#define B_ 8
#define N_ 128
#define M_ 128
#define E_ 256
#define H_ 512

// ---------------- scratch (no allocations allowed) ----------------
__device__ float g_tn[B_ * N_ * E_];   // l2-normalized track features
__device__ float g_dn[B_ * M_ * E_];   // l2-normalized det features
__device__ float g_A [B_ * N_ * H_];   // t_n @ W1[0:E]   + b1
__device__ float g_Bv[B_ * M_ * H_];   // d_m @ W1[E:2E]
// W1c^T single fp16: per 64-k chunk, 512 rows (h) x 128B (64 fp16 k), swizzled
__device__ __align__(16) unsigned char g_W[4 * 65536];

// XOR bits[4:6] of the 128B row offset with (row & 7)
#define SWZ(o) ((o) ^ (((o) >> 3) & 0x70))

__device__ __forceinline__ uint32_t smem_u32(const void* p) {
    uint32_t a;
    asm("{ .reg .u64 t; cvta.to.shared.u64 t, %1; cvt.u32.u64 %0, t; }" : "=r"(a) : "l"(p));
    return a;
}
__device__ __forceinline__ uint32_t pk2h(__half a, __half b) {
    return (uint32_t)__half_as_ushort(a) | ((uint32_t)__half_as_ushort(b) << 16);
}
#define CP_ASYNC16(dst, src) \
    asm volatile("cp.async.cg.shared.global [%0], [%1], 16;" :: "r"(dst), "l"(src) : "memory")
#define CP_COMMIT() asm volatile("cp.async.commit_group;" ::: "memory")
#define CP_WAIT0()  asm volatile("cp.async.wait_group 0;" ::: "memory")

#define LDMX4(r0, r1, r2, r3, addr) \
    asm volatile("ldmatrix.sync.aligned.m8n8.x4.shared.b16 {%0,%1,%2,%3}, [%4];" \
                 : "=r"(r0), "=r"(r1), "=r"(r2), "=r"(r3) : "r"(addr))

__device__ __forceinline__ void mma16816(float* d, const uint32_t* a,
                                         uint32_t b0, uint32_t b1) {
    asm volatile("mma.sync.aligned.m16n8k16.row.col.f32.f16.f16.f32 "
                 "{%0,%1,%2,%3}, {%4,%5,%6,%7}, {%8,%9}, {%0,%1,%2,%3};"
                 : "+f"(d[0]), "+f"(d[1]), "+f"(d[2]), "+f"(d[3])
                 : "r"(a[0]), "r"(a[1]), "r"(a[2]), "r"(a[3]), "r"(b0), "r"(b1));
}

// ---------------- kernel 1: L2 normalize (blocks 0..2047) + W prep (blocks 2048..2079) ----------------
__global__ __launch_bounds__(256) void k_prep(const float* __restrict__ t,
                                              const float* __restrict__ d,
                                              const float* __restrict__ W1) {
    __shared__ float sh[64][65];
    const int tid = threadIdx.x;
    if (blockIdx.x < 2048) {
        int row = blockIdx.x;
        const float* src;
        float* dst;
        if (row < B_ * N_) { src = t + row * E_;            dst = g_tn + row * E_; }
        else               { int r = row - B_ * N_;
                             src = d + r * E_;              dst = g_dn + r * E_; }
        float x = src[tid];
        float s = x * x;
        #pragma unroll
        for (int o = 16; o > 0; o >>= 1) s += __shfl_xor_sync(0xffffffffu, s, o);
        if ((tid & 31) == 0) sh[0][tid >> 5] = s;
        __syncthreads();
        float tot = 0.f;
        #pragma unroll
        for (int i = 0; i < 8; i++) tot += sh[0][i];
        float inv = 1.f / fmaxf(sqrtf(tot), 1e-12f);
        dst[tid] = x * inv;
    } else {
        // W1c^T -> single fp16, swizzled. blk -> (c: 64-k chunk of 4, hb: 64-h block of 8)
        const int blk = blockIdx.x - 2048;
        const int c = blk & 3, hb = blk >> 2;
        {
            int kk0 = tid >> 6, hl = tid & 63;
            #pragma unroll
            for (int it = 0; it < 16; it++) {
                int k = kk0 + it * 4;
                sh[k][hl] = W1[(2 * E_ + c * 64 + k) * H_ + hb * 64 + hl];
            }
        }
        __syncthreads();
        const int hl = tid >> 2, jj = tid & 3;   // h row, 16-k slice
        const int h = hb * 64 + hl;
        #pragma unroll
        for (int s = 0; s < 2; s++) {
            uint32_t w_[4];
            #pragma unroll
            for (int i = 0; i < 4; i++) {
                int k = jj * 16 + s * 8 + i * 2;
                w_[i] = pk2h(__float2half(sh[k][hl]), __float2half(sh[k + 1][hl]));
            }
            *(uint4*)(g_W + c * 65536 + SWZ(h * 128 + jj * 32 + s * 16)) =
                make_uint4(w_[0], w_[1], w_[2], w_[3]);
        }
    }
}

// ---------------- kernel 2: A = t@W1a + b1 ; Bv = d@W1b ----------------
__global__ __launch_bounds__(256) void k_ab(const float* __restrict__ W1,
                                            const float* __restrict__ b1) {
    const int z    = blockIdx.y;
    const int row0 = blockIdx.x * 16;
    const float* X = z ? g_dn : g_tn;
    float*       O = z ? g_Bv : g_A;
    const float* W = W1 + z * (E_ * H_);

    __shared__ float xs[16][17];
    __shared__ float wc[16][H_];

    const int tid = threadIdx.x, w = tid >> 5, l = tid & 31;
    float acc[2][16];
    #pragma unroll
    for (int r = 0; r < 2; r++)
        #pragma unroll
        for (int j = 0; j < 16; j++) acc[r][j] = 0.f;

    for (int c = 0; c < 16; c++) {
        __syncthreads();
        {
            int kk = tid >> 4, r = tid & 15;
            xs[kk][r] = X[(row0 + r) * E_ + c * 16 + kk];
        }
        {
            const float4* src = (const float4*)(W + c * 16 * H_);
            float4* dstp = (float4*)&wc[0][0];
            #pragma unroll
            for (int u = 0; u < 8; u++) dstp[tid + 256 * u] = src[tid + 256 * u];
        }
        __syncthreads();
        #pragma unroll 4
        for (int kk = 0; kk < 16; kk++) {
            float a0 = xs[kk][w * 2 + 0];
            float a1 = xs[kk][w * 2 + 1];
            #pragma unroll
            for (int j = 0; j < 16; j++) {
                float bv = wc[kk][l + 32 * j];
                acc[0][j] = fmaf(a0, bv, acc[0][j]);
                acc[1][j] = fmaf(a1, bv, acc[1][j]);
            }
        }
    }
    #pragma unroll
    for (int r = 0; r < 2; r++) {
        int row = row0 + w * 2 + r;
        #pragma unroll
        for (int j = 0; j < 16; j++) {
            int h = l + 32 * j;
            float v = acc[r][j] + (z == 0 ? b1[h] : 0.f);
            O[row * H_ + h] = v;
        }
    }
}

// ---------------- kernel 3: fp16 2-pass mma.sync GEMM + fused epilogue ----------------
// CTA = (b, n, m-half): 64 pairs x 512 H, 512 threads / 16 warps.
// Warp tile: mw = wid>>3 (32 m), hq = wid&7 (64 h). K = 4 chunks of 64.
// A split fp16 hi/lo (built on the fly), W single fp16 (preprocessed).
enum {
    OFF_W    = 0,        // 2 x 64KB  W chunk double buffer
    OFF_A    = 131072,   // 2 x 16KB  A chunk double buffer (hi 8KB | lo 8KB)
    OFF_TS   = 163840,   // 1KB  t row
    OFF_AS   = 164864,   // 2KB  A row
    OFF_GAM  = 166912,   // 2KB
    OFF_BET  = 168960,   // 2KB
    OFF_W2   = 171008,   // 2KB
    OFF_RED1 = 173056,   // 2KB  [8 hq][64 m]
    OFF_RED2 = 175104,   // 2KB
    SMEM_SZ  = 177152
};

__global__ void __launch_bounds__(512, 1) k_main(const float* __restrict__ gamma,
                                                 const float* __restrict__ beta,
                                                 const float* __restrict__ W2,
                                                 const float* __restrict__ b2,
                                                 float* __restrict__ out) {
    extern __shared__ __align__(16) char smem[];
    const uint32_t sbase = smem_u32(smem);
    const int tid = threadIdx.x, wid = tid >> 5, lid = tid & 31;
    const int b = blockIdx.z, n = blockIdx.y, m0 = blockIdx.x * 64;
    const int mw = wid >> 3, hq = wid & 7;

    float* ts   = (float*)(smem + OFF_TS);
    float* as_  = (float*)(smem + OFF_AS);
    float* gam  = (float*)(smem + OFF_GAM);
    float* bet  = (float*)(smem + OFF_BET);
    float* w2s  = (float*)(smem + OFF_W2);
    float* red1 = (float*)(smem + OFF_RED1);
    float* red2 = (float*)(smem + OFF_RED2);

    if (tid < 256) ts[tid] = g_tn[(b * N_ + n) * E_ + tid];
    {
        int h = tid;
        as_[h] = g_A[(b * N_ + n) * H_ + h];
        gam[h] = gamma[h];
        bet[h] = beta[h];
        w2s[h] = W2[h];
    }

    // ---- chunk loaders ----
    const int am = tid >> 3, aj = tid & 7;   // A-build: m row (64), 8-k slice (8)
    const float* drowA = g_dn + (b * M_ + m0 + am) * E_;
    const uint32_t a_sw = SWZ((uint32_t)(am * 128 + aj * 16));

    auto storeA = [&](int c, int buf, float4 dv0, float4 dv1) {
        const float* tp = ts + c * 64 + aj * 8;
        float x[8];
        x[0] = fabsf(tp[0] - dv0.x); x[1] = fabsf(tp[1] - dv0.y);
        x[2] = fabsf(tp[2] - dv0.z); x[3] = fabsf(tp[3] - dv0.w);
        x[4] = fabsf(tp[4] - dv1.x); x[5] = fabsf(tp[5] - dv1.y);
        x[6] = fabsf(tp[6] - dv1.z); x[7] = fabsf(tp[7] - dv1.w);
        uint32_t hi[4], lo[4];
        #pragma unroll
        for (int i = 0; i < 4; i++) {
            __half h0 = __float2half(x[2 * i + 0]);
            __half h1 = __float2half(x[2 * i + 1]);
            __half l0 = __float2half(x[2 * i + 0] - __half2float(h0));
            __half l1 = __float2half(x[2 * i + 1] - __half2float(h1));
            hi[i] = pk2h(h0, h1);
            lo[i] = pk2h(l0, l1);
        }
        char* abuf = smem + OFF_A + buf * 16384;
        *(uint4*)(abuf + a_sw)        = make_uint4(hi[0], hi[1], hi[2], hi[3]);
        *(uint4*)(abuf + 8192 + a_sw) = make_uint4(lo[0], lo[1], lo[2], lo[3]);
    };
    auto loadW = [&](int c, int buf) {
        const char* src = (const char*)g_W + c * 65536 + tid * 16;
        uint32_t dst = sbase + OFF_W + buf * 65536 + tid * 16;
        #pragma unroll
        for (int u = 0; u < 8; u++)
            CP_ASYNC16(dst + u * 8192, src + u * 8192);
    };

    // ---- accumulators + ldmatrix addressing ----
    float acc[2][8][4];
    #pragma unroll
    for (int mt = 0; mt < 2; mt++)
        #pragma unroll
        for (int nt = 0; nt < 8; nt++)
            #pragma unroll
            for (int r = 0; r < 4; r++) acc[mt][nt][r] = 0.f;

    // A: lanes 0-7 (m0-7,klo), 8-15 (m8-15,klo), 16-23 (m0-7,khi), 24-31 (m8-15,khi)
    const uint32_t arowoff = (uint32_t)(mw * 32 + (lid & 15)) * 128;
    const uint32_t asel    = (uint32_t)(lid >> 4) * 16;
    // B: lanes 0-7 (n0-7,klo), 8-15 (n0-7,khi), 16-23 (n8-15,klo), 24-31 (n8-15,khi)
    const uint32_t browoff = (uint32_t)(hq * 64 + (lid & 7) + ((lid >> 4) << 3)) * 128;
    const uint32_t bsel    = (uint32_t)((lid >> 3) & 1) * 16;
    const uint32_t xr      = (uint32_t)(lid & 7) << 4;

    auto gemm = [&](int buf) {
        const uint32_t aBase = sbase + OFF_A + buf * 16384 + arowoff;
        const uint32_t bBase = sbase + OFF_W + buf * 65536 + browoff;
        #pragma unroll
        for (int ks = 0; ks < 4; ks++) {
            const uint32_t ao = (ks * 32 + asel) ^ xr;
            const uint32_t bo = (ks * 32 + bsel) ^ xr;
            uint32_t ah[2][4], al[2][4];
            #pragma unroll
            for (int mt = 0; mt < 2; mt++) {
                LDMX4(ah[mt][0], ah[mt][1], ah[mt][2], ah[mt][3], aBase + mt * 2048 + ao);
                LDMX4(al[mt][0], al[mt][1], al[mt][2], al[mt][3], aBase + 8192 + mt * 2048 + ao);
            }
            #pragma unroll
            for (int np = 0; np < 4; np++) {
                uint32_t bf[4];
                LDMX4(bf[0], bf[1], bf[2], bf[3], bBase + np * 2048 + bo);
                const int nt = np * 2;
                #pragma unroll
                for (int mt = 0; mt < 2; mt++) {
                    mma16816(acc[mt][nt + 0], ah[mt], bf[0], bf[1]);
                    mma16816(acc[mt][nt + 1], ah[mt], bf[2], bf[3]);
                    mma16816(acc[mt][nt + 0], al[mt], bf[0], bf[1]);
                    mma16816(acc[mt][nt + 1], al[mt], bf[2], bf[3]);
                }
            }
        }
    };

    // ---- software-pipelined K loop (4 chunks of 64) ----
    float4 pf0, pf1;
    pf0 = *(const float4*)(drowA + aj * 8);
    pf1 = *(const float4*)(drowA + aj * 8 + 4);
    loadW(0, 0);
    CP_COMMIT();
    __syncthreads();            // ts ready (also orders initial smem fills)
    storeA(0, 0, pf0, pf1);
    CP_WAIT0();
    __syncthreads();
    #pragma unroll
    for (int c = 0; c < 4; c++) {
        const int buf = c & 1;
        if (c < 3) {
            loadW(c + 1, buf ^ 1);
            CP_COMMIT();
            pf0 = *(const float4*)(drowA + (c + 1) * 64 + aj * 8);       // LDG issued early,
            pf1 = *(const float4*)(drowA + (c + 1) * 64 + aj * 8 + 4);   // consumed after gemm
        }
        gemm(buf);
        if (c < 3) {
            storeA(c + 1, buf ^ 1, pf0, pf1);
            CP_WAIT0();
        }
        __syncthreads();
    }

    // ---- fused epilogue ----
    const float b2v = b2[0];
    float s1[2][2] = {{0.f, 0.f}, {0.f, 0.f}};
    float s2[2][2] = {{0.f, 0.f}, {0.f, 0.f}};
    const int mbase = m0 + mw * 32;
    #pragma unroll
    for (int mt = 0; mt < 2; mt++) {
        #pragma unroll
        for (int half = 0; half < 2; half++) {
            const int mr = mt * 16 + (lid >> 2) + half * 8;
            const float* bp = g_Bv + (b * M_ + mbase + mr) * H_ + hq * 64 + (lid & 3) * 2;
            #pragma unroll
            for (int nt = 0; nt < 8; nt++) {
                float2 bv = *(const float2*)(bp + nt * 8);
                int h = hq * 64 + nt * 8 + (lid & 3) * 2;
                float v0 = acc[mt][nt][half * 2 + 0] + as_[h + 0] + bv.x;
                float v1 = acc[mt][nt][half * 2 + 1] + as_[h + 1] + bv.y;
                acc[mt][nt][half * 2 + 0] = v0;
                acc[mt][nt][half * 2 + 1] = v1;
                s1[mt][half] += v0 + v1;
                s2[mt][half] = fmaf(v0, v0, fmaf(v1, v1, s2[mt][half]));
            }
        }
    }
    #pragma unroll
    for (int mt = 0; mt < 2; mt++)
        #pragma unroll
        for (int half = 0; half < 2; half++)
            #pragma unroll
            for (int o = 1; o <= 2; o <<= 1) {
                s1[mt][half] += __shfl_xor_sync(0xffffffffu, s1[mt][half], o);
                s2[mt][half] += __shfl_xor_sync(0xffffffffu, s2[mt][half], o);
            }
    if ((lid & 3) == 0) {
        #pragma unroll
        for (int mt = 0; mt < 2; mt++)
            #pragma unroll
            for (int half = 0; half < 2; half++) {
                int m = mw * 32 + mt * 16 + (lid >> 2) + half * 8;
                red1[hq * 64 + m] = s1[mt][half];
                red2[hq * 64 + m] = s2[mt][half];
            }
    }
    __syncthreads();
    float mu[2][2], inv[2][2];
    #pragma unroll
    for (int mt = 0; mt < 2; mt++)
        #pragma unroll
        for (int half = 0; half < 2; half++) {
            int m = mw * 32 + mt * 16 + (lid >> 2) + half * 8;
            float S1 = 0.f, S2 = 0.f;
            #pragma unroll
            for (int q = 0; q < 8; q++) {
                S1 += red1[q * 64 + m];
                S2 += red2[q * 64 + m];
            }
            float mm = S1 * (1.f / 512.f);
            mu[mt][half]  = mm;
            inv[mt][half] = rsqrtf(fmaxf(S2 * (1.f / 512.f) - mm * mm, 0.f) + 1e-5f);
        }
    __syncthreads();

    float o_[2][2] = {{0.f, 0.f}, {0.f, 0.f}};
    #pragma unroll
    for (int mt = 0; mt < 2; mt++) {
        #pragma unroll
        for (int half = 0; half < 2; half++) {
            float mm = mu[mt][half], iv = inv[mt][half];
            #pragma unroll
            for (int nt = 0; nt < 8; nt++) {
                int h = hq * 64 + nt * 8 + (lid & 3) * 2;
                #pragma unroll
                for (int e = 0; e < 2; e++) {
                    float v = acc[mt][nt][half * 2 + e];
                    float x = fmaf((v - mm) * iv, gam[h + e], bet[h + e]);
                    float sg = 1.f / (1.f + __expf(-x));
                    o_[mt][half] = fmaf(x * sg, w2s[h + e], o_[mt][half]);
                }
            }
        }
    }
    #pragma unroll
    for (int mt = 0; mt < 2; mt++)
        #pragma unroll
        for (int half = 0; half < 2; half++)
            #pragma unroll
            for (int o = 1; o <= 2; o <<= 1)
                o_[mt][half] += __shfl_xor_sync(0xffffffffu, o_[mt][half], o);
    if ((lid & 3) == 0) {
        #pragma unroll
        for (int mt = 0; mt < 2; mt++)
            #pragma unroll
            for (int half = 0; half < 2; half++) {
                int m = mw * 32 + mt * 16 + (lid >> 2) + half * 8;
                red1[hq * 64 + m] = o_[mt][half];
            }
    }
    __syncthreads();
    if (tid < 64) {
        int m = tid;
        float oo = b2v;
        #pragma unroll
        for (int q = 0; q < 8; q++) oo += red1[q * 64 + m];
        out[(b * N_ + n) * M_ + m0 + m] = oo;
    }
}

// ---------------- launch ----------------
extern "C" void kernel_launch(void* const* d_in, const int* in_sizes, int n_in,
                              void* d_out, int out_size) {
    const float* t     = (const float*)d_in[0];
    const float* d     = (const float*)d_in[1];
    const float* W1    = (const float*)d_in[2];
    const float* b1    = (const float*)d_in[3];
    const float* gamma = (const float*)d_in[4];
    const float* beta  = (const float*)d_in[5];
    const float* W2    = (const float*)d_in[6];
    const float* b2    = (const float*)d_in[7];
    float* out = (float*)d_out;

    cudaFuncSetAttribute(k_main, cudaFuncAttributeMaxDynamicSharedMemorySize, SMEM_SZ);

    k_prep<<<2048 + 32, 256>>>(t, d, W1);
    k_ab<<<dim3(64, 2), 256>>>(W1, b1);
    k_main<<<dim3(2, N_, B_), 512, SMEM_SZ>>>(gamma, beta, W2, b2, out);
}